// round 16
// baseline (speedup 1.0000x reference)
#include <cuda_runtime.h>
#include <cuda_fp16.h>
#include <stdint.h>

// Problem shape (fixed by reference): B=8, C=256, H=W=64, N=128 cells.
#define BSZ 8
#define CSZ 256
#define PSZ 4096                 // 64*64 pixels per image
#define NSZ 128                  // total cells
#define QSZ 1024                 // pixels per quarter
#define QSTRIDE 1152             // 1024 + 128 pad; *2B = 2304, multiple of 16

// ---- device scratch (static allocation allowed; runtime alloc is not) ----
__device__ __align__(16) unsigned short g_idx[(size_t)NSZ * 4 * QSTRIDE]; // per (cell,quarter) lists
__device__ int g_cnt[NSZ * 4];
__device__ __align__(16) uint4 g_part[4 * NSZ * 32];     // [q][cell][g*2+u] 16-ch fp16 partials

// k_pool4 dynamic smem: fp16 dest (1024 px x 16 ch) + f32 staging tile.
#define DEST_BYTES (QSZ * 16 * 2)                  // 32768
#define TILE_W     260                             // 256 px + 4 pad floats
#define TILE_FLOATS (16 * TILE_W + 16)             // +16: upper 8-row block offset
#define SMEM_TOTAL (DEST_BYTES + TILE_FLOATS * 4)  // 49472

// ---------------------------------------------------------------------------
// Kernel 1: per-(cell, quarter) mask compaction. One 512-thread block per
// cell. Local dtype detection (scan this cell's 1024 32-bit words: int32
// bool masks have all words in {0,1}; packed-byte masks at density 0.25 give
// words>1 w.p. ~1-0.42^1024). Warp-aggregated compaction into 4 quarter
// lists (a warp's 32 chunks always lie in one quarter: 256-word quarters,
// 32-aligned warps). Stores quarter-local pixel indices + 128 pad dups.
// ---------------------------------------------------------------------------
__global__ void __launch_bounds__(512) k_compact(const void* __restrict__ masks) {
    __shared__ int sCnt[4];
    __shared__ int sIsByte;
    const int n = blockIdx.x;
    const int t = threadIdx.x;
    if (t < 4) sCnt[t] = 0;
    if (t == 0) sIsByte = 0;
    __syncthreads();

    const unsigned* mw = (const unsigned*)masks;
    const unsigned loc = mw[(size_t)n * 1024 + t] | mw[(size_t)n * 1024 + 512 + t];
    if (loc > 1u) sIsByte = 1;                   // benign race, same value
    __syncthreads();
    const int isByte = sIsByte;

    const int lane = t & 31;
#pragma unroll
    for (int it = 0; it < 2; ++it) {
        const int chunk = it * 512 + t;          // word 0..1023 -> pixels 4*chunk..+3
        const int q     = chunk >> 8;            // quarter (warp-uniform)
        unsigned short* lst = g_idx + ((size_t)n * 4 + q) * QSTRIDE;
        unsigned vals[4];
        if (isByte) {
            const unsigned w = mw[(size_t)n * 1024 + chunk];
            vals[0] = w & 0xffu;         vals[1] = (w >> 8) & 0xffu;
            vals[2] = (w >> 16) & 0xffu; vals[3] = w >> 24;
        } else {
            const uint4 w = ((const uint4*)masks)[(size_t)n * 1024 + chunk];
            vals[0] = w.x; vals[1] = w.y; vals[2] = w.z; vals[3] = w.w;
        }
#pragma unroll
        for (int qq = 0; qq < 4; ++qq) {
            const bool set = (vals[qq] != 0);
            unsigned act = __ballot_sync(0xffffffffu, set);
            if (act) {
                int leader = __ffs(act) - 1;
                int base = 0;
                if (lane == leader) base = atomicAdd(&sCnt[q], __popc(act));
                base = __shfl_sync(0xffffffffu, base, leader);
                if (set)
                    lst[base + __popc(act & ((1u << lane) - 1u))] =
                        (unsigned short)((4 * chunk + qq) & (QSZ - 1));   // quarter-local
            }
        }
    }
    __syncthreads();
    if (t < 4) g_cnt[n * 4 + t] = sCnt[t];
    {
        const int q = t >> 7, i = t & 127;       // 128 pads per quarter
        unsigned short* lst = g_idx + ((size_t)n * 4 + q) * QSTRIDE;
        const int c = sCnt[q];
        const unsigned short pad = (c > 0) ? lst[0] : (unsigned short)0;
        lst[c + i] = pad;
    }
}

// ---------------------------------------------------------------------------
// Kernel 2: block = (16-ch group g, image b, pixel-quarter q) -> 512 blocks.
// Phase 1 (4 chunks of 256 px): float4 loads (512B/warp) -> conflict-free
// staging tile -> per-pixel 8-ch fp16 packs -> swizzled pixel-major smem dest.
// Tile upper 8-row block offset +16 floats makes the column gather
// (px + 16u + 4k banks) fully conflict-free across the warp.
// Phase 2: warp w = cell base+w; lanes: u=lane&1 (8-ch pack), sl=lane>>1
// (16 contiguous list slots, multiple of 8). 8 indices per LDG.128, 8
// LDS.128 gathers in two 4-deep batches (reg-pressure friendly), hmax tree,
// shfl butterfly, partial write to g_part. Feature bytes cross DRAM once.
// ---------------------------------------------------------------------------
__device__ __forceinline__ uint4 hmax4(uint4 a, const uint4 b) {
    __half2* pa = (__half2*)&a;
    const __half2* pb = (const __half2*)&b;
    pa[0] = __hmax2(pa[0], pb[0]);
    pa[1] = __hmax2(pa[1], pb[1]);
    pa[2] = __hmax2(pa[2], pb[2]);
    pa[3] = __hmax2(pa[3], pb[3]);
    return a;
}

__global__ void __launch_bounds__(512, 3) k_pool4(const float* __restrict__ feat,
                                                  const int* __restrict__ counts) {
    extern __shared__ __align__(16) char sm[];
    uint4* dest = (uint4*)sm;                         // [2*QSZ] uint4, swizzled
    float* tile = (float*)(sm + DEST_BYTES);

    const int g = blockIdx.x;                         // channel group
    const int b = blockIdx.y;                         // image
    const int q = blockIdx.z;                         // pixel quarter
    const int t = threadIdx.x;

    const float* __restrict__ src =
        feat + ((size_t)b * CSZ + g * 16) * PSZ + q * QSZ;

    // ---------------- phase 1: build fp16 pixel-major dest ----------------
#pragma unroll
    for (int ck = 0; ck < 4; ++ck) {                  // 4 chunks x 256 px
#pragma unroll
        for (int j = 0; j < 2; ++j) {
            const int idx = j * 512 + t;              // 0..1023
            const int c   = idx >> 6;                 // 0..15 (warp-uniform)
            const int f4  = idx & 63;
            const float4 v = *(const float4*)(src + (size_t)c * PSZ + ck * 256 + 4 * f4);
            *(float4*)&tile[c * TILE_W + ((c >= 8) ? 16 : 0) + 4 * f4] = v;
        }
        __syncthreads();
        {
            const int px = t >> 1;                    // 0..255
            const int u  = t & 1;                     // 8-ch pack
            const float* col = &tile[u * (8 * TILE_W + 16) + px];
            const __half2 h0 = __floats2half2_rn(col[0],          col[TILE_W]);
            const __half2 h1 = __floats2half2_rn(col[2 * TILE_W], col[3 * TILE_W]);
            const __half2 h2 = __floats2half2_rn(col[4 * TILE_W], col[5 * TILE_W]);
            const __half2 h3 = __floats2half2_rn(col[6 * TILE_W], col[7 * TILE_W]);
            const int pg = ck * 256 + px;             // quarter-local pixel
            uint4 o;
            o.x = *(const unsigned*)&h0; o.y = *(const unsigned*)&h1;
            o.z = *(const unsigned*)&h2; o.w = *(const unsigned*)&h3;
            dest[2 * pg + (u ^ (pg & 1))] = o;
        }
        __syncthreads();
    }

    // ---------------- phase 2: per-warp cell gather from smem ----------------
    const int w    = t >> 5;
    const int lane = t & 31;
    const int u    = lane & 1;
    const int sl   = lane >> 1;

    int base = 0, cimg = 0;
#pragma unroll
    for (int k = 0; k < BSZ; ++k) {
        const int cv = counts[k];
        if (k < b) base += cv;
        if (k == b) cimg = cv;
    }

    if (w < cimg) {
        const int n   = base + w;
        const int cnt = g_cnt[n * 4 + q];
        const unsigned short* __restrict__ lst =
            g_idx + ((size_t)n * 4 + q) * QSTRIDE;

        const int Lc = 8 * ((cnt + 127) >> 7);        // per-slot chunk, mult of 8
        int k0       = sl * Lc;
        const int ke = k0 + Lc;

        const unsigned NEG = 0xFC00FC00u;             // (-inf,-inf) fp16
        uint4 acc = make_uint4(NEG, NEG, NEG, NEG);

        for (; k0 < ke; k0 += 8) {
            const uint4 iv = *(const uint4*)(lst + k0);   // 8 quarter-local idx
            {
                const int p0 = iv.x & 0xffff, p1 = iv.x >> 16;
                const int p2 = iv.y & 0xffff, p3 = iv.y >> 16;
                uint4 v0 = dest[2 * p0 + (u ^ (p0 & 1))];
                uint4 v1 = dest[2 * p1 + (u ^ (p1 & 1))];
                uint4 v2 = dest[2 * p2 + (u ^ (p2 & 1))];
                uint4 v3 = dest[2 * p3 + (u ^ (p3 & 1))];
                v0 = hmax4(v0, v1); v2 = hmax4(v2, v3);
                acc = hmax4(acc, hmax4(v0, v2));
            }
            {
                const int p4 = iv.z & 0xffff, p5 = iv.z >> 16;
                const int p6 = iv.w & 0xffff, p7 = iv.w >> 16;
                uint4 v4 = dest[2 * p4 + (u ^ (p4 & 1))];
                uint4 v5 = dest[2 * p5 + (u ^ (p5 & 1))];
                uint4 v6 = dest[2 * p6 + (u ^ (p6 & 1))];
                uint4 v7 = dest[2 * p7 + (u ^ (p7 & 1))];
                v4 = hmax4(v4, v5); v6 = hmax4(v6, v7);
                acc = hmax4(acc, hmax4(v4, v6));
            }
        }

        // butterfly over the 16 slots (xor 2,4,8,16 preserves u)
#pragma unroll
        for (int d = 2; d <= 16; d <<= 1) {
            uint4 o;
            o.x = __shfl_xor_sync(0xffffffffu, acc.x, d);
            o.y = __shfl_xor_sync(0xffffffffu, acc.y, d);
            o.z = __shfl_xor_sync(0xffffffffu, acc.z, d);
            o.w = __shfl_xor_sync(0xffffffffu, acc.w, d);
            acc = hmax4(acc, o);
        }

        if (sl == 0)
            g_part[(size_t)q * (NSZ * 32) + n * 32 + g * 2 + u] = acc;
    }
}

// ---------------------------------------------------------------------------
// Kernel 3: combine the 4 quarter partials -> f32 output.
// id = cell*32 + g*2 + u; reads 4 uint4 (stride NSZ*32), hmax, converts
// 8 halves -> 8 floats, writes 32B contiguous per thread (coalesced).
// ---------------------------------------------------------------------------
__global__ void __launch_bounds__(256) k_combine(float* __restrict__ out) {
    const int id = blockIdx.x * 256 + threadIdx.x;    // 0..4095
    uint4 r = g_part[id];
    r = hmax4(r, g_part[NSZ * 32 + id]);
    r = hmax4(r, g_part[2 * NSZ * 32 + id]);
    r = hmax4(r, g_part[3 * NSZ * 32 + id]);

    const __half2* h = (const __half2*)&r;
    const float2 f0 = __half22float2(h[0]);
    const float2 f1 = __half22float2(h[1]);
    const float2 f2 = __half22float2(h[2]);
    const float2 f3 = __half22float2(h[3]);
    const int n = id >> 5;
    float* o = out + (size_t)n * CSZ + (id & 31) * 8;
    *(float4*)o       = make_float4(f0.x, f0.y, f1.x, f1.y);
    *(float4*)(o + 4) = make_float4(f2.x, f2.y, f3.x, f3.y);
}

// ---------------------------------------------------------------------------
// Launch. Inputs (metadata order): feature_maps f32, cell_masks bool
// (int32 or packed bytes — auto-detected per cell block), cell_counts i32.
// Output: f32 (N, C).
// ---------------------------------------------------------------------------
extern "C" void kernel_launch(void* const* d_in, const int* in_sizes, int n_in,
                              void* d_out, int out_size) {
    const float* feat   = (const float*)d_in[0];
    const void*  masks  = d_in[1];
    const int*   counts = (const int*)d_in[2];
    float*       out    = (float*)d_out;

    // idempotent, non-allocating, capture-safe
    cudaFuncSetAttribute(k_pool4, cudaFuncAttributeMaxDynamicSharedMemorySize,
                         SMEM_TOTAL);

    k_compact<<<NSZ, 512>>>(masks);
    k_pool4<<<dim3(16, BSZ, 4), 512, SMEM_TOTAL>>>(feat, counts);
    k_combine<<<16, 256>>>(out);
}

// round 17
// speedup vs baseline: 1.0013x; 1.0013x over previous
#include <cuda_runtime.h>
#include <cuda_fp16.h>
#include <stdint.h>

// Problem shape (fixed by reference): B=8, C=256, H=W=64, N=128 cells.
#define BSZ 8
#define CSZ 256
#define PSZ 4096                 // 64*64 pixels per image
#define NSZ 128                  // total cells
#define QSZ 1024                 // pixels per quarter
#define QSTRIDE 1152             // 1024 + 128 pad; *2B = 2304, multiple of 16

// ---- device scratch (static allocation allowed; runtime alloc is not) ----
__device__ __align__(16) unsigned short g_idx[(size_t)NSZ * 4 * QSTRIDE]; // per (cell,quarter) lists
__device__ int g_cnt[NSZ * 4];
__device__ __align__(16) uint4 g_part[4 * NSZ * 32];     // [q][cell][g*2+u] 16-ch fp16 partials

// k_pool4 dynamic smem: fp16 dest (1024 px x 16 ch) + f32 staging tile.
#define DEST_BYTES (QSZ * 16 * 2)                  // 32768
#define TILE_W     260                             // 256 px + 4 pad floats
#define TILE_FLOATS (16 * TILE_W + 16)             // +16: upper 8-row block offset
#define SMEM_TOTAL (DEST_BYTES + TILE_FLOATS * 4)  // 49472

// ---------------------------------------------------------------------------
// Kernel 1: per-(cell, quarter) mask compaction. One 512-thread block per
// cell. Local dtype detection (scan this cell's 1024 32-bit words: int32
// bool masks have all words in {0,1}; packed-byte masks at density 0.25 give
// words>1 w.p. ~1-0.42^1024). Warp-aggregated compaction into 4 quarter
// lists (a warp's 32 chunks always lie in one quarter: 256-word quarters,
// 32-aligned warps). Stores quarter-local pixel indices + 128 pad dups.
// ---------------------------------------------------------------------------
__global__ void __launch_bounds__(512) k_compact(const void* __restrict__ masks) {
    __shared__ int sCnt[4];
    __shared__ int sIsByte;
    const int n = blockIdx.x;
    const int t = threadIdx.x;
    if (t < 4) sCnt[t] = 0;
    if (t == 0) sIsByte = 0;
    __syncthreads();

    const unsigned* mw = (const unsigned*)masks;
    const unsigned loc = mw[(size_t)n * 1024 + t] | mw[(size_t)n * 1024 + 512 + t];
    if (loc > 1u) sIsByte = 1;                   // benign race, same value
    __syncthreads();
    const int isByte = sIsByte;

    const int lane = t & 31;
#pragma unroll
    for (int it = 0; it < 2; ++it) {
        const int chunk = it * 512 + t;          // word 0..1023 -> pixels 4*chunk..+3
        const int q     = chunk >> 8;            // quarter (warp-uniform)
        unsigned short* lst = g_idx + ((size_t)n * 4 + q) * QSTRIDE;
        unsigned vals[4];
        if (isByte) {
            const unsigned w = mw[(size_t)n * 1024 + chunk];
            vals[0] = w & 0xffu;         vals[1] = (w >> 8) & 0xffu;
            vals[2] = (w >> 16) & 0xffu; vals[3] = w >> 24;
        } else {
            const uint4 w = ((const uint4*)masks)[(size_t)n * 1024 + chunk];
            vals[0] = w.x; vals[1] = w.y; vals[2] = w.z; vals[3] = w.w;
        }
#pragma unroll
        for (int qq = 0; qq < 4; ++qq) {
            const bool set = (vals[qq] != 0);
            unsigned act = __ballot_sync(0xffffffffu, set);
            if (act) {
                int leader = __ffs(act) - 1;
                int base = 0;
                if (lane == leader) base = atomicAdd(&sCnt[q], __popc(act));
                base = __shfl_sync(0xffffffffu, base, leader);
                if (set)
                    lst[base + __popc(act & ((1u << lane) - 1u))] =
                        (unsigned short)((4 * chunk + qq) & (QSZ - 1));   // quarter-local
            }
        }
    }
    __syncthreads();
    if (t < 4) g_cnt[n * 4 + t] = sCnt[t];
    {
        const int q = t >> 7, i = t & 127;       // 128 pads per quarter
        unsigned short* lst = g_idx + ((size_t)n * 4 + q) * QSTRIDE;
        const int c = sCnt[q];
        const unsigned short pad = (c > 0) ? lst[0] : (unsigned short)0;
        lst[c + i] = pad;
    }
}

// ---------------------------------------------------------------------------
// Kernel 2: block = (16-ch group g, image b, pixel-quarter q) -> 512 blocks.
// Phase 1 (4 chunks of 256 px): float4 loads (512B/warp) -> conflict-free
// staging tile -> per-pixel 8-ch fp16 packs -> swizzled pixel-major smem dest.
// Tile upper 8-row block offset +16 floats makes the column gather
// (px + 16u + 4k banks) fully conflict-free across the warp.
// Phase 2: warp w = cell base+w; lanes: u=lane&1 (8-ch pack), sl=lane>>1
// (16 contiguous list slots, multiple of 8). 8 indices per LDG.128, 8
// LDS.128 gathers in two 4-deep batches (reg-pressure friendly), hmax tree,
// shfl butterfly, partial write to g_part. Feature bytes cross DRAM once.
// ---------------------------------------------------------------------------
__device__ __forceinline__ uint4 hmax4(uint4 a, const uint4 b) {
    __half2* pa = (__half2*)&a;
    const __half2* pb = (const __half2*)&b;
    pa[0] = __hmax2(pa[0], pb[0]);
    pa[1] = __hmax2(pa[1], pb[1]);
    pa[2] = __hmax2(pa[2], pb[2]);
    pa[3] = __hmax2(pa[3], pb[3]);
    return a;
}

__global__ void __launch_bounds__(512, 3) k_pool4(const float* __restrict__ feat,
                                                  const int* __restrict__ counts) {
    extern __shared__ __align__(16) char sm[];
    uint4* dest = (uint4*)sm;                         // [2*QSZ] uint4, swizzled
    float* tile = (float*)(sm + DEST_BYTES);

    const int g = blockIdx.x;                         // channel group
    const int b = blockIdx.y;                         // image
    const int q = blockIdx.z;                         // pixel quarter
    const int t = threadIdx.x;

    const float* __restrict__ src =
        feat + ((size_t)b * CSZ + g * 16) * PSZ + q * QSZ;

    // ---------------- phase 1: build fp16 pixel-major dest ----------------
#pragma unroll
    for (int ck = 0; ck < 4; ++ck) {                  // 4 chunks x 256 px
#pragma unroll
        for (int j = 0; j < 2; ++j) {
            const int idx = j * 512 + t;              // 0..1023
            const int c   = idx >> 6;                 // 0..15 (warp-uniform)
            const int f4  = idx & 63;
            const float4 v = *(const float4*)(src + (size_t)c * PSZ + ck * 256 + 4 * f4);
            *(float4*)&tile[c * TILE_W + ((c >= 8) ? 16 : 0) + 4 * f4] = v;
        }
        __syncthreads();
        {
            const int px = t >> 1;                    // 0..255
            const int u  = t & 1;                     // 8-ch pack
            const float* col = &tile[u * (8 * TILE_W + 16) + px];
            const __half2 h0 = __floats2half2_rn(col[0],          col[TILE_W]);
            const __half2 h1 = __floats2half2_rn(col[2 * TILE_W], col[3 * TILE_W]);
            const __half2 h2 = __floats2half2_rn(col[4 * TILE_W], col[5 * TILE_W]);
            const __half2 h3 = __floats2half2_rn(col[6 * TILE_W], col[7 * TILE_W]);
            const int pg = ck * 256 + px;             // quarter-local pixel
            uint4 o;
            o.x = *(const unsigned*)&h0; o.y = *(const unsigned*)&h1;
            o.z = *(const unsigned*)&h2; o.w = *(const unsigned*)&h3;
            dest[2 * pg + (u ^ (pg & 1))] = o;
        }
        __syncthreads();
    }

    // ---------------- phase 2: per-warp cell gather from smem ----------------
    const int w    = t >> 5;
    const int lane = t & 31;
    const int u    = lane & 1;
    const int sl   = lane >> 1;

    int base = 0, cimg = 0;
#pragma unroll
    for (int k = 0; k < BSZ; ++k) {
        const int cv = counts[k];
        if (k < b) base += cv;
        if (k == b) cimg = cv;
    }

    if (w < cimg) {
        const int n   = base + w;
        const int cnt = g_cnt[n * 4 + q];
        const unsigned short* __restrict__ lst =
            g_idx + ((size_t)n * 4 + q) * QSTRIDE;

        const int Lc = 8 * ((cnt + 127) >> 7);        // per-slot chunk, mult of 8
        int k0       = sl * Lc;
        const int ke = k0 + Lc;

        const unsigned NEG = 0xFC00FC00u;             // (-inf,-inf) fp16
        uint4 acc = make_uint4(NEG, NEG, NEG, NEG);

        for (; k0 < ke; k0 += 8) {
            const uint4 iv = *(const uint4*)(lst + k0);   // 8 quarter-local idx
            {
                const int p0 = iv.x & 0xffff, p1 = iv.x >> 16;
                const int p2 = iv.y & 0xffff, p3 = iv.y >> 16;
                uint4 v0 = dest[2 * p0 + (u ^ (p0 & 1))];
                uint4 v1 = dest[2 * p1 + (u ^ (p1 & 1))];
                uint4 v2 = dest[2 * p2 + (u ^ (p2 & 1))];
                uint4 v3 = dest[2 * p3 + (u ^ (p3 & 1))];
                v0 = hmax4(v0, v1); v2 = hmax4(v2, v3);
                acc = hmax4(acc, hmax4(v0, v2));
            }
            {
                const int p4 = iv.z & 0xffff, p5 = iv.z >> 16;
                const int p6 = iv.w & 0xffff, p7 = iv.w >> 16;
                uint4 v4 = dest[2 * p4 + (u ^ (p4 & 1))];
                uint4 v5 = dest[2 * p5 + (u ^ (p5 & 1))];
                uint4 v6 = dest[2 * p6 + (u ^ (p6 & 1))];
                uint4 v7 = dest[2 * p7 + (u ^ (p7 & 1))];
                v4 = hmax4(v4, v5); v6 = hmax4(v6, v7);
                acc = hmax4(acc, hmax4(v4, v6));
            }
        }

        // butterfly over the 16 slots (xor 2,4,8,16 preserves u)
#pragma unroll
        for (int d = 2; d <= 16; d <<= 1) {
            uint4 o;
            o.x = __shfl_xor_sync(0xffffffffu, acc.x, d);
            o.y = __shfl_xor_sync(0xffffffffu, acc.y, d);
            o.z = __shfl_xor_sync(0xffffffffu, acc.z, d);
            o.w = __shfl_xor_sync(0xffffffffu, acc.w, d);
            acc = hmax4(acc, o);
        }

        if (sl == 0)
            g_part[(size_t)q * (NSZ * 32) + n * 32 + g * 2 + u] = acc;
    }
}

// ---------------------------------------------------------------------------
// Kernel 3: combine the 4 quarter partials -> f32 output.
// id = cell*32 + g*2 + u; reads 4 uint4 (stride NSZ*32), hmax, converts
// 8 halves -> 8 floats, writes 32B contiguous per thread (coalesced).
// ---------------------------------------------------------------------------
__global__ void __launch_bounds__(256) k_combine(float* __restrict__ out) {
    const int id = blockIdx.x * 256 + threadIdx.x;    // 0..4095
    uint4 r = g_part[id];
    r = hmax4(r, g_part[NSZ * 32 + id]);
    r = hmax4(r, g_part[2 * NSZ * 32 + id]);
    r = hmax4(r, g_part[3 * NSZ * 32 + id]);

    const __half2* h = (const __half2*)&r;
    const float2 f0 = __half22float2(h[0]);
    const float2 f1 = __half22float2(h[1]);
    const float2 f2 = __half22float2(h[2]);
    const float2 f3 = __half22float2(h[3]);
    const int n = id >> 5;
    float* o = out + (size_t)n * CSZ + (id & 31) * 8;
    *(float4*)o       = make_float4(f0.x, f0.y, f1.x, f1.y);
    *(float4*)(o + 4) = make_float4(f2.x, f2.y, f3.x, f3.y);
}

// ---------------------------------------------------------------------------
// Launch. Inputs (metadata order): feature_maps f32, cell_masks bool
// (int32 or packed bytes — auto-detected per cell block), cell_counts i32.
// Output: f32 (N, C).
// ---------------------------------------------------------------------------
extern "C" void kernel_launch(void* const* d_in, const int* in_sizes, int n_in,
                              void* d_out, int out_size) {
    const float* feat   = (const float*)d_in[0];
    const void*  masks  = d_in[1];
    const int*   counts = (const int*)d_in[2];
    float*       out    = (float*)d_out;

    // idempotent, non-allocating, capture-safe
    cudaFuncSetAttribute(k_pool4, cudaFuncAttributeMaxDynamicSharedMemorySize,
                         SMEM_TOTAL);

    k_compact<<<NSZ, 512>>>(masks);
    k_pool4<<<dim3(16, BSZ, 4), 512, SMEM_TOTAL>>>(feat, counts);
    k_combine<<<16, 256>>>(out);
}